// round 3
// baseline (speedup 1.0000x reference)
#include <cuda_runtime.h>
#include <math.h>

#define BT 192
#define NSEQ 207
#define CDIM 128
#define RED 64
#define DIN 128
#define DS 16
#define NTOK (BT*NSEQ)   // 39744
#define SCAN_STRIDE 288  // u[128] dt[128] B[16] C[16]

// scratch (device globals; no allocation allowed)
__device__ float g_h[NTOK*RED];                 // 10.2 MB
__device__ float g_uraw[2][NTOK*DIN];           // 40.7 MB
__device__ float g_z[2][NTOK*DIN];              // 40.7 MB
__device__ float g_scan[2L*BT*NSEQ*SCAN_STRIDE];// 91.6 MB (scan order)
__device__ float g_ypre[2][NTOK*DIN];           // 40.7 MB
__device__ float g_ysum[NTOK*RED];              // 10.2 MB

// ---------------------------------------------------------------------------
// K1: h = LN256(concat(x,qk)) @ in_w + in_b -> g_h
// 256 thr, 32 tokens/block. LN per-warp (no block sync). GEMM: q=tid&3,j=tid>>2
// ---------------------------------------------------------------------------
__global__ __launch_bounds__(256) void k1_ln_inproj(
    const float* __restrict__ x, const float* __restrict__ qk,
    const float* __restrict__ lnw, const float* __restrict__ lnb,
    const float* __restrict__ w, const float* __restrict__ b)
{
  __shared__ float sn[32][256];
  __shared__ float slw[256], slb[256], sb[64];
  int tid = threadIdx.x;
  int lane = tid & 31, wid = tid >> 5;
  int base = blockIdx.x * 32;
  slw[tid] = lnw[tid]; slb[tid] = lnb[tid];
  if (tid < 64) sb[tid] = b[tid];
  int q = tid & 3, j = tid >> 2;
  float wr[64];
  #pragma unroll
  for (int i = 0; i < 64; i++) wr[i] = w[(q*64+i)*64 + j];
  __syncthreads();

  #pragma unroll
  for (int r = 0; r < 4; r++) {
    int tokl = wid*4 + r;
    int tok = base + tokl;
    float v[8]; float s = 0.f, s2 = 0.f;
    #pragma unroll
    for (int i = 0; i < 8; i++) {
      v[i] = (i < 4) ? x[tok*128 + i*32 + lane] : qk[tok*128 + (i-4)*32 + lane];
      s += v[i]; s2 += v[i]*v[i];
    }
    #pragma unroll
    for (int o = 16; o; o >>= 1) {
      s  += __shfl_xor_sync(~0u, s,  o);
      s2 += __shfl_xor_sync(~0u, s2, o);
    }
    float m = s * (1.f/256.f);
    float rs = rsqrtf(s2 * (1.f/256.f) - m*m + 1e-5f);
    #pragma unroll
    for (int i = 0; i < 8; i++) {
      int k = i*32 + lane;
      sn[tokl][k] = (v[i] - m)*rs*slw[k] + slb[k];
    }
  }
  __syncthreads();

  for (int it = 0; it < 32; it++) {
    const float4* s4 = (const float4*)&sn[it][q*64];
    float acc = 0.f;
    #pragma unroll
    for (int i = 0; i < 16; i++) {
      float4 hv = s4[i];
      acc += hv.x*wr[4*i] + hv.y*wr[4*i+1] + hv.z*wr[4*i+2] + hv.w*wr[4*i+3];
    }
    acc += __shfl_xor_sync(~0u, acc, 1);
    acc += __shfl_xor_sync(~0u, acc, 2);
    if (q == 0) g_h[(base+it)*64 + j] = acc + sb[j];
  }
}

// ---------------------------------------------------------------------------
// K2a: u_raw = h @ inproj[:, :128], z = h @ inproj[:, 128:256], per dir.
// grid (1242, 2), 256 thr, 32 tokens/block. q=tid&1 (k-half), j=tid>>1.
// ---------------------------------------------------------------------------
__global__ __launch_bounds__(256) void k2a_uz(
    const float* __restrict__ ip0, const float* __restrict__ ip1)
{
  __shared__ float sh[32][64];
  int dir = blockIdx.y;
  const float* inproj = dir ? ip1 : ip0;
  int tid = threadIdx.x;
  int base = blockIdx.x * 32;
  ((float4*)sh)[tid]       = ((const float4*)(g_h + base*64))[tid];
  ((float4*)sh)[tid + 256] = ((const float4*)(g_h + base*64))[tid + 256];
  int q = tid & 1, j = tid >> 1;
  float wu[32], wz[32];
  #pragma unroll
  for (int i = 0; i < 32; i++) {
    wu[i] = inproj[(q*32+i)*256 + j];
    wz[i] = inproj[(q*32+i)*256 + 128 + j];
  }
  __syncthreads();
  for (int it = 0; it < 32; it++) {
    const float4* h4 = (const float4*)&sh[it][q*32];
    float au = 0.f, az = 0.f;
    #pragma unroll
    for (int i = 0; i < 8; i++) {
      float4 hv = h4[i];
      au += hv.x*wu[4*i] + hv.y*wu[4*i+1] + hv.z*wu[4*i+2] + hv.w*wu[4*i+3];
      az += hv.x*wz[4*i] + hv.y*wz[4*i+1] + hv.z*wz[4*i+2] + hv.w*wz[4*i+3];
    }
    au += __shfl_xor_sync(~0u, au, 1);
    az += __shfl_xor_sync(~0u, az, 1);
    if (q == 0) {
      g_uraw[dir][(base+it)*128 + j] = au;
      g_z[dir][(base+it)*128 + j]    = az;
    }
  }
}

// ---------------------------------------------------------------------------
// K2c: conv+silu -> u; xdbl = u @ xproj; dt = softplus(xdbl[:4]@dtw + dtb).
// Writes packed g_scan rows in SCAN ORDER (bw rows reversed).
// grid (7, 192, 2), 256 thr, dynamic smem.
// ---------------------------------------------------------------------------
#define C_RAW  0        // 38*128 = 4864
#define C_SU   4864     // 32*128 = 4096
#define C_XT   8960     // 36*132 = 4752
#define C_DT4  13712    // 32*4   = 128
#define C_CW   13840    // 512
#define C_CB   14352    // 128
#define C_DTW  14480    // 512
#define C_DTB  14992    // 128
#define C_TOT  15120
#define C_BYTES (C_TOT*4)

extern __shared__ float smc[];

__global__ __launch_bounds__(256) void k2c_prep(
    const float* __restrict__ xp0, const float* __restrict__ cw0, const float* __restrict__ cb0,
    const float* __restrict__ dw0, const float* __restrict__ db0,
    const float* __restrict__ xp1, const float* __restrict__ cw1, const float* __restrict__ cb1,
    const float* __restrict__ dw1, const float* __restrict__ db1)
{
  int tile = blockIdx.x, seq = blockIdx.y, dir = blockIdx.z;
  const float* xproj = dir ? xp1 : xp0;
  const float* convw = dir ? cw1 : cw0;
  const float* convb = dir ? cb1 : cb0;
  const float* dtw   = dir ? dw1 : dw0;
  const float* dtb   = dir ? db1 : db0;
  int tid = threadIdx.x;
  int t0 = tile * 32;
  int nt = NSEQ - t0; if (nt > 32) nt = 32;
  float* srow_base = g_scan + ((size_t)(dir*BT + seq))*NSEQ*SCAN_STRIDE;

  // loads
  for (int idx = tid; idx < 38*128; idx += 256) {
    int row = idx >> 7, d = idx & 127;
    int t = t0 - 3 + row;
    smc[C_RAW + idx] = (t >= 0 && t < NSEQ) ? g_uraw[dir][(seq*NSEQ + t)*128 + d] : 0.f;
  }
  for (int idx = tid; idx < 128*36; idx += 256) {
    int d = idx / 36, jj = idx % 36;
    smc[C_XT + jj*132 + d] = xproj[idx];
  }
  for (int idx = tid; idx < 512; idx += 256) { smc[C_CW + idx] = convw[idx]; smc[C_DTW + idx] = dtw[idx]; }
  if (tid < 128) { smc[C_CB + tid] = convb[tid]; smc[C_DTB + tid] = dtb[tid]; }
  __syncthreads();

  // conv + silu -> su + g_scan u field
  for (int o = tid; o < 32*128; o += 256) {
    int tl = o >> 7, d = o & 127;
    if (tl < nt) {
      float s = smc[C_CB + d];
      if (dir == 0) {
        #pragma unroll
        for (int k = 0; k < 4; k++) s += smc[C_CW + d*4 + k] * smc[C_RAW + (tl+k)*128 + d];
      } else {
        #pragma unroll
        for (int k = 0; k < 4; k++) s += smc[C_CW + d*4 + k] * smc[C_RAW + (tl+6-k)*128 + d];
      }
      s = s / (1.f + __expf(-s));
      smc[C_SU + tl*128 + d] = s;
      int t = t0 + tl;
      int rr = dir ? (NSEQ-1-t) : t;
      srow_base[(size_t)rr*SCAN_STRIDE + d] = s;
    }
  }
  __syncthreads();

  // xdbl GEMM
  if (tid < 252) {
    int jj = tid % 36, tl0 = tid / 36;
    for (int tl = tl0; tl < nt; tl += 7) {
      const float4* u4 = (const float4*)&smc[C_SU + tl*128];
      const float4* w4 = (const float4*)&smc[C_XT + jj*132];
      float acc = 0.f;
      #pragma unroll
      for (int i = 0; i < 32; i++) {
        float4 uv = u4[i]; float4 wv = w4[i];
        acc += uv.x*wv.x + uv.y*wv.y + uv.z*wv.z + uv.w*wv.w;
      }
      if (jj < 4) smc[C_DT4 + tl*4 + jj] = acc;
      else {
        int t = t0 + tl;
        int rr = dir ? (NSEQ-1-t) : t;
        int field = (jj < 20) ? (256 + jj - 4) : (272 + jj - 20);
        srow_base[(size_t)rr*SCAN_STRIDE + field] = acc;
      }
    }
  }
  __syncthreads();

  // dt = softplus(dt4 @ dtw + dtb)
  for (int o = tid; o < 32*128; o += 256) {
    int tl = o >> 7, d = o & 127;
    if (tl < nt) {
      float xdt = smc[C_DTB + d]
        + smc[C_DT4 + tl*4 + 0]*smc[C_DTW + 0*128 + d]
        + smc[C_DT4 + tl*4 + 1]*smc[C_DTW + 1*128 + d]
        + smc[C_DT4 + tl*4 + 2]*smc[C_DTW + 2*128 + d]
        + smc[C_DT4 + tl*4 + 3]*smc[C_DTW + 3*128 + d];
      float dt = (xdt > 20.f) ? xdt : log1pf(__expf(xdt));
      int t = t0 + tl;
      int rr = dir ? (NSEQ-1-t) : t;
      srow_base[(size_t)rr*SCAN_STRIDE + 128 + d] = dt;
    }
  }
}

// ---------------------------------------------------------------------------
// K2d: selective scan. grid (192,2), 512 thr. d=tid>>2, p=tid&3.
// Double-buffered 8-step chunks. exp(-dt) powers trick (A[d][n]=-(n+1)).
// ---------------------------------------------------------------------------
__global__ __launch_bounds__(512) void k2d_scan(
    const float* __restrict__ al0, const float* __restrict__ dp0,
    const float* __restrict__ al1, const float* __restrict__ dp1)
{
  __shared__ float sbuf[2][8*SCAN_STRIDE];  // 2*2304
  __shared__ float syb[8*128];
  int seq = blockIdx.x, dir = blockIdx.y;
  const float* Alog = dir ? al1 : al0;
  const float* Dp   = dir ? dp1 : dp0;
  int tid = threadIdx.x;
  int d = tid >> 2, p = tid & 3;
  float Ar[4]; bool fast = true;
  #pragma unroll
  for (int i = 0; i < 4; i++) {
    Ar[i] = -__expf(Alog[d*16 + p*4 + i]);
    fast = fast && (fabsf(Ar[i] + (float)(p*4 + i + 1)) < 1e-3f);
  }
  float Dd = Dp[d];
  const float* base = g_scan + ((size_t)(dir*BT + seq))*NSEQ*SCAN_STRIDE;
  float* ypbase = &g_ypre[dir][seq*NSEQ*128];

  // preload chunk 0
  {
    const float4* src = (const float4*)base;
    if (tid < 576) ((float4*)sbuf[0])[tid] = src[tid];
    if (tid + 512 < 576) ((float4*)sbuf[0])[tid+512] = src[tid+512];
  }
  __syncthreads();

  float hs0 = 0.f, hs1 = 0.f, hs2 = 0.f, hs3 = 0.f;
  for (int c = 0; c < 26; c++) {
    int cb = c & 1;
    int ns = NSEQ - c*8; if (ns > 8) ns = 8;
    // prefetch next chunk into regs
    float4 pf0, pf1; int cnt = 0;
    if (c < 25) {
      int ns2 = NSEQ - (c+1)*8; if (ns2 > 8) ns2 = 8;
      cnt = ns2 * (SCAN_STRIDE/4);
      const float4* src = (const float4*)(base + (size_t)(c+1)*8*SCAN_STRIDE);
      if (tid < cnt) pf0 = src[tid];
      if (tid + 512 < cnt) pf1 = src[tid+512];
    }
    const float* bb = sbuf[cb];
    for (int s = 0; s < ns; s++) {
      float u  = bb[s*SCAN_STRIDE + d];
      float dt = bb[s*SCAN_STRIDE + 128 + d];
      float4 Bv = *(const float4*)&bb[s*SCAN_STRIDE + 256 + p*4];
      float4 Cv = *(const float4*)&bb[s*SCAN_STRIDE + 272 + p*4];
      float du = dt * u;
      float m1, m2, m3, m4;
      if (fast) {
        float e1 = __expf(-dt);
        float e2 = e1*e1, e4 = e2*e2, e8 = e4*e4;
        float bse = (p == 0) ? 1.f : (p == 1) ? e4 : (p == 2) ? e8 : e8*e4;
        m1 = bse*e1; m2 = m1*e1; m3 = m2*e1; m4 = m3*e1;
      } else {
        m1 = __expf(dt*Ar[0]); m2 = __expf(dt*Ar[1]);
        m3 = __expf(dt*Ar[2]); m4 = __expf(dt*Ar[3]);
      }
      hs0 = hs0*m1 + du*Bv.x; float yy = hs0*Cv.x;
      hs1 = hs1*m2 + du*Bv.y; yy += hs1*Cv.y;
      hs2 = hs2*m3 + du*Bv.z; yy += hs2*Cv.z;
      hs3 = hs3*m4 + du*Bv.w; yy += hs3*Cv.w;
      yy += __shfl_xor_sync(~0u, yy, 1);
      yy += __shfl_xor_sync(~0u, yy, 2);
      if (p == 0) syb[s*128 + d] = yy + u*Dd;
    }
    if (cnt) {
      float4* dst = (float4*)sbuf[1-cb];
      if (tid < cnt) dst[tid] = pf0;
      if (tid + 512 < cnt) dst[tid+512] = pf1;
    }
    __syncthreads();
    // flush ypre rows (un-reverse for bw)
    if (tid < ns*32) {
      int row = tid >> 5;
      int t = c*8 + row;
      int to = dir ? (NSEQ-1-t) : t;
      ((float4*)(ypbase + (size_t)to*128))[tid & 31] = ((float4*)syb)[tid];
    }
    __syncthreads();
  }
}

// ---------------------------------------------------------------------------
// K6: yg = ypre * silu(z); ysum = sum_dir yg @ outproj_dir. 256 thr, 32 tok.
// ---------------------------------------------------------------------------
__global__ __launch_bounds__(256) void k6_gate_out(
    const float* __restrict__ op0, const float* __restrict__ op1)
{
  __shared__ float sy[2*32*128];
  int tid = threadIdx.x;
  int base = blockIdx.x * 32;
  for (int i = tid; i < 2048; i += 256) {
    int dir2 = i >> 10, rem = i & 1023;
    float4 yp = ((const float4*)(g_ypre[dir2] + base*128))[rem];
    float4 zz = ((const float4*)(g_z[dir2] + base*128))[rem];
    float4 yg;
    yg.x = yp.x * (zz.x / (1.f + __expf(-zz.x)));
    yg.y = yp.y * (zz.y / (1.f + __expf(-zz.y)));
    yg.z = yp.z * (zz.z / (1.f + __expf(-zz.z)));
    yg.w = yp.w * (zz.w / (1.f + __expf(-zz.w)));
    ((float4*)sy)[i] = yg;
  }
  int q = tid & 3, j = tid >> 2;
  float w0[32], w1[32];
  #pragma unroll
  for (int i = 0; i < 32; i++) {
    w0[i] = op0[(q*32+i)*64 + j];
    w1[i] = op1[(q*32+i)*64 + j];
  }
  __syncthreads();
  for (int it = 0; it < 32; it++) {
    const float4* a4 = (const float4*)&sy[it*128 + q*32];
    const float4* b4 = (const float4*)&sy[4096 + it*128 + q*32];
    float acc = 0.f;
    #pragma unroll
    for (int i = 0; i < 8; i++) {
      float4 av = a4[i];
      acc += av.x*w0[4*i] + av.y*w0[4*i+1] + av.z*w0[4*i+2] + av.w*w0[4*i+3];
      float4 bv = b4[i];
      acc += bv.x*w1[4*i] + bv.y*w1[4*i+1] + bv.z*w1[4*i+2] + bv.w*w1[4*i+3];
    }
    acc += __shfl_xor_sync(~0u, acc, 1);
    acc += __shfl_xor_sync(~0u, acc, 2);
    if (q == 0) g_ysum[(base+it)*64 + j] = acc;
  }
}

// ---------------------------------------------------------------------------
// K3: LN64(ysum) @ ov_w + ov_b; + x; LN128 @ o_w + o_b  (float4 smem reads)
// ---------------------------------------------------------------------------
__global__ __launch_bounds__(256) void k3_out(
  const float* __restrict__ x,
  const float* __restrict__ ovlnw, const float* __restrict__ ovlnb,
  const float* __restrict__ ovw, const float* __restrict__ ovb,
  const float* __restrict__ olnw, const float* __restrict__ olnb,
  const float* __restrict__ ow, const float* __restrict__ ob,
  float* __restrict__ out)
{
  __shared__ float syn[32*64];
  __shared__ float sr[32*128];
  int tid = threadIdx.x;
  int lane = tid & 31, wid = tid >> 5;
  int base = blockIdx.x * 32;
  int kh = tid & 1, c = tid >> 1;
  float ovr[32], owr[64];
  #pragma unroll
  for (int i = 0; i < 32; i++) ovr[i] = ovw[(kh*32+i)*128 + c];
  #pragma unroll
  for (int i = 0; i < 64; i++) owr[i] = ow[(kh*64+i)*128 + c];
  float ovbc = ovb[c], obc = ob[c];

  for (int r = 0; r < 4; r++) {
    int tl = r*8 + wid;
    int tok = base + tl;
    float v0 = g_ysum[tok*64 + lane];
    float v1 = g_ysum[tok*64 + 32 + lane];
    float s = v0 + v1, s2 = v0*v0 + v1*v1;
    #pragma unroll
    for (int o = 16; o; o >>= 1) {
      s  += __shfl_xor_sync(~0u, s,  o);
      s2 += __shfl_xor_sync(~0u, s2, o);
    }
    float m = s * (1.f/64.f);
    float rs = rsqrtf(s2 * (1.f/64.f) - m*m + 1e-5f);
    syn[tl*64 + lane]      = (v0 - m)*rs*ovlnw[lane]    + ovlnb[lane];
    syn[tl*64 + 32 + lane] = (v1 - m)*rs*ovlnw[32+lane] + ovlnb[32+lane];
  }
  __syncthreads();

  for (int tl = 0; tl < 32; tl++) {
    int tok = base + tl;
    const float4* sy4 = (const float4*)&syn[tl*64 + kh*32];
    float acc = 0.f;
    #pragma unroll
    for (int i = 0; i < 8; i++) {
      float4 sv = sy4[i];
      acc += sv.x*ovr[4*i] + sv.y*ovr[4*i+1] + sv.z*ovr[4*i+2] + sv.w*ovr[4*i+3];
    }
    acc += __shfl_xor_sync(~0u, acc, 1);
    if (kh == 0) sr[tl*128 + c] = acc + ovbc + x[tok*128 + c];
  }
  __syncthreads();

  for (int r = 0; r < 4; r++) {
    int tl = r*8 + wid;
    float v[4]; float s = 0.f, s2 = 0.f;
    #pragma unroll
    for (int i = 0; i < 4; i++) {
      v[i] = sr[tl*128 + i*32 + lane];
      s += v[i]; s2 += v[i]*v[i];
    }
    #pragma unroll
    for (int o = 16; o; o >>= 1) {
      s  += __shfl_xor_sync(~0u, s,  o);
      s2 += __shfl_xor_sync(~0u, s2, o);
    }
    float m = s * (1.f/128.f);
    float rs = rsqrtf(s2 * (1.f/128.f) - m*m + 1e-5f);
    #pragma unroll
    for (int i = 0; i < 4; i++) {
      int k = i*32 + lane;
      sr[tl*128 + k] = (v[i] - m)*rs*olnw[k] + olnb[k];
    }
  }
  __syncthreads();

  for (int tl = 0; tl < 32; tl++) {
    int tok = base + tl;
    const float4* sv4 = (const float4*)&sr[tl*128 + kh*64];
    float acc = 0.f;
    #pragma unroll
    for (int i = 0; i < 16; i++) {
      float4 sv = sv4[i];
      acc += sv.x*owr[4*i] + sv.y*owr[4*i+1] + sv.z*owr[4*i+2] + sv.w*owr[4*i+3];
    }
    acc += __shfl_xor_sync(~0u, acc, 1);
    if (kh == 0) out[tok*128 + c] = acc + obc;
  }
}

// ---------------------------------------------------------------------------
extern "C" void kernel_launch(void* const* d_in, const int* in_sizes, int n_in,
                              void* d_out, int out_size) {
  const float* x      = (const float*)d_in[0];
  const float* qk     = (const float*)d_in[1];
  const float* in_lnw = (const float*)d_in[2];
  const float* in_lnb = (const float*)d_in[3];
  const float* in_w   = (const float*)d_in[4];
  const float* in_b   = (const float*)d_in[5];

  const float *fw[9], *bw[9];
  const float *ovlnw, *ovlnb, *ovw, *ovb, *olnw, *olnb, *ow, *ob;

  if (in_sizes[6] == 64 && in_sizes[14] == 16384) {
    // dict-insertion order
    ovlnw = (const float*)d_in[6];  ovlnb = (const float*)d_in[7];
    ovw   = (const float*)d_in[8];  ovb   = (const float*)d_in[9];
    olnw  = (const float*)d_in[10]; olnb  = (const float*)d_in[11];
    ow    = (const float*)d_in[12]; ob    = (const float*)d_in[13];
    for (int i = 0; i < 9; i++) {
      fw[i] = (const float*)d_in[14 + i];
      bw[i] = (const float*)d_in[23 + i];
    }
  } else {
    for (int i = 0; i < 9; i++) {
      fw[i] = (const float*)d_in[6 + i];
      bw[i] = (const float*)d_in[15 + i];
    }
    ovlnw = (const float*)d_in[24]; ovlnb = (const float*)d_in[25];
    ovw   = (const float*)d_in[26]; ovb   = (const float*)d_in[27];
    olnw  = (const float*)d_in[28]; olnb  = (const float*)d_in[29];
    ow    = (const float*)d_in[30]; ob    = (const float*)d_in[31];
  }
  float* out = (float*)d_out;

  // fw/bw order: inproj, conv_w, conv_b, xproj, dtw, dtb, Alog, D, outproj
  cudaFuncSetAttribute(k2c_prep, cudaFuncAttributeMaxDynamicSharedMemorySize, C_BYTES);

  k1_ln_inproj<<<NTOK/32, 256>>>(x, qk, in_lnw, in_lnb, in_w, in_b);

  k2a_uz<<<dim3(NTOK/32, 2), 256>>>(fw[0], bw[0]);

  k2c_prep<<<dim3(7, BT, 2), 256, C_BYTES>>>(
      fw[3], fw[1], fw[2], fw[4], fw[5],
      bw[3], bw[1], bw[2], bw[4], bw[5]);

  k2d_scan<<<dim3(BT, 2), 512>>>(fw[6], fw[7], bw[6], bw[7]);

  k6_gate_out<<<NTOK/32, 256>>>(fw[8], bw[8]);

  k3_out<<<NTOK/32, 256>>>(x, ovlnw, ovlnb, ovw, ovb, olnw, olnb, ow, ob, out);
}